// round 14
// baseline (speedup 1.0000x reference)
#include <cuda_runtime.h>
#include <cuda_fp16.h>
#include <math.h>

#define NMAX 50000
#define EMAX 800000
#define DDIM 64

#define SBLK 1024
#define NSB ((NMAX + SBLK - 1) / SBLK)     // 49

// scratch (zero-initialized at load; invariants restored every execution)
__device__ float  g_h[(size_t)NMAX * DDIM];    // fp32 h (self/skip term)
__device__ __half g_hh[(size_t)NMAX * DDIM];   // fp16 h (neighbor gather)
__device__ int    g_cnt[NMAX];                 // degrees (re-zeroed by gather)
__device__ int    g_off[NMAX];                 // CSR offsets
__device__ int    g_fill[NMAX];                // fill cursors
__device__ unsigned long long g_aggf[NSB];     // scan aggregates (reset by fill)
__device__ uint2  g_edges[EMAX];               // (src, w) grouped by dst

// packed f32x2 FMA (FFMA2) — PTX-only; identical fp32 numerics.
#define FMA_F32X2(acc, a, b) \
    asm("fma.rn.f32x2 %0, %1, %2, %0;" : "+l"(acc) : "l"(a), "l"(b))
#define PACK_F32X2(out, lo, hi) \
    asm("mov.b64 %0, {%1, %2};" : "=l"(out) : "r"(lo), "r"(hi))
#define UNPACK_F32X2(lo, hi, in) \
    asm("mov.b64 {%0, %1}, %2;" : "=r"(lo), "=r"(hi) : "l"(in))

// ---------------------------------------------------------------------------
// Kernel 1: h = X @ W^T -> g_h (fp32) + g_hh (fp16); fused degree histogram.
// ---------------------------------------------------------------------------
#define XSTR 132
#define WSTR 68
#define GBLKS ((NMAX + 127) / 128)   // 391

__global__ void __launch_bounds__(256) gemm_kernel(
    const float* __restrict__ X, const float* __restrict__ W,
    const int* __restrict__ edst, int E, int n)
{
    __shared__ float sW[DDIM * WSTR];
    __shared__ float sX[DDIM * XSTR];

    const int tid  = threadIdx.x;
    const int row0 = blockIdx.x * 128;

    // fused histogram (fire-and-forget REDs; g_cnt zero at entry)
    for (int i = blockIdx.x * 256 + tid; i < E; i += GBLKS * 256)
        atomicAdd(&g_cnt[edst[i]], 1);

    #pragma unroll
    for (int i = 0; i < 16; i++) {
        int idx = tid + i * 256;
        int o = idx >> 6, d = idx & 63;
        sW[d * WSTR + o] = W[idx];
    }
    #pragma unroll
    for (int i = 0; i < 32; i++) {
        int idx = tid + i * 256;
        int r = idx >> 6, d = idx & 63;
        int gr = row0 + r;
        sX[d * XSTR + r] = (gr < n) ? X[(size_t)gr * DDIM + d] : 0.0f;
    }
    __syncthreads();

    const int tx = tid & 15;
    const int ty = tid >> 4;
    const int o0 = tx * 4;
    const int r0 = ty * 8;

    unsigned long long accp[8][2];
    #pragma unroll
    for (int i = 0; i < 8; i++) { accp[i][0] = 0ULL; accp[i][1] = 0ULL; }

    #pragma unroll 16
    for (int d = 0; d < DDIM; d++) {
        float4 xa = *reinterpret_cast<const float4*>(&sX[d * XSTR + r0]);
        float4 xb = *reinterpret_cast<const float4*>(&sX[d * XSTR + r0 + 4]);
        ulonglong2 wp = *reinterpret_cast<const ulonglong2*>(&sW[d * WSTR + o0]);
        float x[8] = {xa.x, xa.y, xa.z, xa.w, xb.x, xb.y, xb.z, xb.w};
        #pragma unroll
        for (int i = 0; i < 8; i++) {
            unsigned xu = __float_as_uint(x[i]);
            unsigned long long xx;
            PACK_F32X2(xx, xu, xu);
            FMA_F32X2(accp[i][0], xx, wp.x);
            FMA_F32X2(accp[i][1], xx, wp.y);
        }
    }

    #pragma unroll
    for (int i = 0; i < 8; i++) {
        int gr = row0 + r0 + i;
        if (gr < n) {
            unsigned u0, u1, u2, u3;
            UNPACK_F32X2(u0, u1, accp[i][0]);
            UNPACK_F32X2(u2, u3, accp[i][1]);
            float4 hv = make_float4(__uint_as_float(u0), __uint_as_float(u1),
                                    __uint_as_float(u2), __uint_as_float(u3));
            *reinterpret_cast<float4*>(&g_h[(size_t)gr * DDIM + o0]) = hv;
            __half2* dst2 = reinterpret_cast<__half2*>(&g_hh[(size_t)gr * DDIM + o0]);
            dst2[0] = __float22half2_rn(make_float2(hv.x, hv.y));
            dst2[1] = __float22half2_rn(make_float2(hv.z, hv.w));
        }
    }
}

// ---------------------------------------------------------------------------
// Kernel 2: single-pass exclusive scan of g_cnt -> g_off / g_fill.
// (49 blocks, all wave-1 resident; packed value+flag, proven in R7/R8.)
// ---------------------------------------------------------------------------
__global__ void __launch_bounds__(256) scan_kernel(int n)
{
    __shared__ int sv[256];
    __shared__ int sbase;
    const int b = blockIdx.x, t = threadIdx.x;
    const int base = b * SBLK + t * 4;

    int c[4];
    int s = 0;
    #pragma unroll
    for (int k = 0; k < 4; k++) {
        int i = base + k;
        c[k] = (i < n) ? g_cnt[i] : 0;
        s += c[k];
    }
    sv[t] = s;
    if (t == 0) sbase = 0;
    __syncthreads();
    #pragma unroll
    for (int off = 1; off < 256; off <<= 1) {
        int u = (t >= off) ? sv[t - off] : 0;
        __syncthreads();
        sv[t] += u;
        __syncthreads();
    }

    if (t == 0) {
        unsigned long long v = (1ULL << 32) | (unsigned)sv[255];
        atomicExch(&g_aggf[b], v);
    }
    __syncthreads();

    if (t < b) {
        unsigned long long v;
        do {
            v = *((volatile unsigned long long*)&g_aggf[t]);
        } while (!(v >> 32));
        atomicAdd(&sbase, (int)(unsigned)v);
    }
    __syncthreads();

    int run = sbase + sv[t] - s;
    #pragma unroll
    for (int k = 0; k < 4; k++) {
        int i = base + k;
        if (i < n) {
            g_off[i]  = run;
            g_fill[i] = run;
            run += c[k];
        }
    }
}

// ---------------------------------------------------------------------------
// Kernel 3: fill CSR edge array; reset scan flags for next replay.
// ---------------------------------------------------------------------------
__global__ void fill_kernel(const int* __restrict__ src,
                            const int* __restrict__ dst,
                            const float* __restrict__ ew, int E)
{
    int i = blockIdx.x * blockDim.x + threadIdx.x;
    if (i < NSB) g_aggf[i] = 0ULL;
    if (i < E) {
        int d = dst[i];
        int slot = atomicAdd(&g_fill[d], 1);
        g_edges[slot] = make_uint2((unsigned)src[i], __float_as_uint(ew[i]));
    }
}

// ---------------------------------------------------------------------------
// Kernel 4: gather + skip + bias + SELU, NO atomics, NO shfl.
// Warp per node; metas staged in per-warp smem (LDS-broadcast, rt=2cyc)
// then h-row LDGs issued in unrolled batches of 8 (MLP 8 per warp).
// ---------------------------------------------------------------------------
#define GW 8   // warps per block

__global__ void __launch_bounds__(256) gather_kernel(
    const float* __restrict__ bias,
    const float* __restrict__ skipw,
    float* __restrict__ out, int n)
{
    __shared__ uint2 smeta[GW][64];

    const int warp = threadIdx.x >> 5;
    const int lane = threadIdx.x & 31;
    const int node = blockIdx.x * GW + warp;
    if (node >= n) return;

    const int start = g_off[node];
    const int deg   = g_cnt[node];
    if (lane == 0) g_cnt[node] = 0;   // restore zero invariant

    const __half2* hh2 = reinterpret_cast<const __half2*>(g_hh);

    float2 acc = make_float2(0.0f, 0.0f);

    for (int base = 0; base < deg; base += 64) {
        const int m = min(deg - base, 64);

        // stage metas: coalesced LDG -> STS (2 iterations max)
        for (int k = lane; k < m; k += 32)
            smeta[warp][k] = __ldg(&g_edges[start + base + k]);
        __syncwarp();

        int k = 0;
        for (; k + 8 <= m; k += 8) {
            #pragma unroll
            for (int j = 0; j < 8; j++) {
                uint2 mm = smeta[warp][k + j];          // LDS broadcast
                float2 hv = __half22float2(
                    __ldg(&hh2[(size_t)mm.x * 32 + lane]));
                float w = __uint_as_float(mm.y);
                acc.x = fmaf(w, hv.x, acc.x);
                acc.y = fmaf(w, hv.y, acc.y);
            }
        }
        for (; k < m; k++) {
            uint2 mm = smeta[warp][k];
            float2 hv = __half22float2(
                __ldg(&hh2[(size_t)mm.x * 32 + lane]));
            float w = __uint_as_float(mm.y);
            acc.x = fmaf(w, hv.x, acc.x);
            acc.y = fmaf(w, hv.y, acc.y);
        }
        __syncwarp();
    }

    const int col = lane * 2;
    const float2 hself = *reinterpret_cast<const float2*>(&g_h[(size_t)node * DDIM + col]);
    const float2 sw = *reinterpret_cast<const float2*>(&skipw[col]);
    const float2 bv = *reinterpret_cast<const float2*>(&bias[col]);

    float vx = fmaf(hself.x, sw.x, acc.x) + bv.x;
    float vy = fmaf(hself.y, sw.y, acc.y) + bv.y;

    const float scale = 1.0507009873554805f;
    const float alpha = 1.6732632423543772f;
    vx = vx > 0.0f ? scale * vx : scale * alpha * (expf(vx) - 1.0f);
    vy = vy > 0.0f ? scale * vy : scale * alpha * (expf(vy) - 1.0f);

    *reinterpret_cast<float2*>(&out[(size_t)node * DDIM + col]) = make_float2(vx, vy);
}

extern "C" void kernel_launch(void* const* d_in, const int* in_sizes, int n_in,
                              void* d_out, int out_size)
{
    const float* features = (const float*)d_in[0];
    const float* W        = (const float*)d_in[1];
    const float* bias     = (const float*)d_in[2];
    const float* skipw    = (const float*)d_in[3];
    const float* ew       = (const float*)d_in[4];
    const int*   esrc     = (const int*)d_in[5];
    const int*   edst     = (const int*)d_in[6];
    float* out = (float*)d_out;

    const int n = in_sizes[0] / DDIM;     // 50000
    const int E = in_sizes[4];            // 800000

    // 1. GEMM (+ fused degree histogram)
    gemm_kernel<<<GBLKS, 256>>>(features, W, edst, E, n);

    // 2. single-pass scan -> CSR offsets
    scan_kernel<<<NSB, 256>>>(n);

    // 3. fill CSR edge array (+ reset scan flags)
    fill_kernel<<<(E + 511) / 512, 512>>>(esrc, edst, ew, E);

    // 4. atomic-free gather + skip + bias + SELU (+ reset counts)
    gather_kernel<<<(n + GW - 1) / GW, 256>>>(bias, skipw, out, n);
}

// round 15
// speedup vs baseline: 1.5470x; 1.5470x over previous
#include <cuda_runtime.h>
#include <cuda_fp16.h>
#include <math.h>

#define NMAX 50000
#define EMAX 800000
#define DDIM 64

#define SBLK 1024
#define NSB ((NMAX + SBLK - 1) / SBLK)     // 49

// scratch (zero-initialized at load; invariants restored every run)
__device__ __half g_hh[(size_t)NMAX * DDIM];   // fp16 h (gather side)
__device__ int    g_cnt[NMAX];                 // degrees (zeroed by selu)
__device__ int    g_off[NMAX];                 // CSR offsets
__device__ int    g_fill[NMAX];                // fill cursors
__device__ unsigned long long g_aggf[NSB];     // scan aggregates (reset by fill)
__device__ uint2  g_edges[EMAX];               // (src, w) grouped by dst
__device__ int    g_edst[EMAX];                // dst per grouped edge

// packed f32x2 FMA (FFMA2) — PTX-only; identical fp32 numerics.
#define FMA_F32X2(acc, a, b) \
    asm("fma.rn.f32x2 %0, %1, %2, %0;" : "+l"(acc) : "l"(a), "l"(b))
#define PACK_F32X2(out, lo, hi) \
    asm("mov.b64 %0, {%1, %2};" : "=l"(out) : "r"(lo), "r"(hi))
#define UNPACK_F32X2(lo, hi, in) \
    asm("mov.b64 {%0, %1}, %2;" : "=r"(lo), "=r"(hi) : "l"(in))

// ---------------------------------------------------------------------------
// Kernel 1: h = X @ W^T; out = h*skip + bias (fp32); g_hh = h (fp16);
// fused degree histogram. (R12 gemm structure, measured 16.6us + hist.)
// ---------------------------------------------------------------------------
#define XSTR 132
#define WSTR 68
#define GBLKS ((NMAX + 127) / 128)   // 391

__global__ void __launch_bounds__(256) gemm_skip_kernel(
    const float* __restrict__ X, const float* __restrict__ W,
    const float* __restrict__ bias, const float* __restrict__ skipw,
    const int* __restrict__ edst,
    float* __restrict__ out, int E, int n)
{
    __shared__ float sW[DDIM * WSTR];
    __shared__ float sX[DDIM * XSTR];

    const int tid  = threadIdx.x;
    const int row0 = blockIdx.x * 128;

    // fused histogram (fire-and-forget; g_cnt zero at entry)
    for (int i = blockIdx.x * 256 + tid; i < E; i += GBLKS * 256)
        atomicAdd(&g_cnt[edst[i]], 1);

    #pragma unroll
    for (int i = 0; i < 16; i++) {
        int idx = tid + i * 256;
        int o = idx >> 6, d = idx & 63;
        sW[d * WSTR + o] = W[idx];
    }
    #pragma unroll
    for (int i = 0; i < 32; i++) {
        int idx = tid + i * 256;
        int r = idx >> 6, d = idx & 63;
        int gr = row0 + r;
        sX[d * XSTR + r] = (gr < n) ? X[(size_t)gr * DDIM + d] : 0.0f;
    }
    __syncthreads();

    const int tx = tid & 15;
    const int ty = tid >> 4;
    const int o0 = tx * 4;
    const int r0 = ty * 8;

    unsigned long long accp[8][2];
    #pragma unroll
    for (int i = 0; i < 8; i++) { accp[i][0] = 0ULL; accp[i][1] = 0ULL; }

    #pragma unroll 16
    for (int d = 0; d < DDIM; d++) {
        float4 xa = *reinterpret_cast<const float4*>(&sX[d * XSTR + r0]);
        float4 xb = *reinterpret_cast<const float4*>(&sX[d * XSTR + r0 + 4]);
        ulonglong2 wp = *reinterpret_cast<const ulonglong2*>(&sW[d * WSTR + o0]);
        float x[8] = {xa.x, xa.y, xa.z, xa.w, xb.x, xb.y, xb.z, xb.w};
        #pragma unroll
        for (int i = 0; i < 8; i++) {
            unsigned xu = __float_as_uint(x[i]);
            unsigned long long xx;
            PACK_F32X2(xx, xu, xu);
            FMA_F32X2(accp[i][0], xx, wp.x);
            FMA_F32X2(accp[i][1], xx, wp.y);
        }
    }

    const float4 swv = *reinterpret_cast<const float4*>(&skipw[o0]);
    const float4 bvv = *reinterpret_cast<const float4*>(&bias[o0]);

    #pragma unroll
    for (int i = 0; i < 8; i++) {
        int gr = row0 + r0 + i;
        if (gr < n) {
            unsigned u0, u1, u2, u3;
            UNPACK_F32X2(u0, u1, accp[i][0]);
            UNPACK_F32X2(u2, u3, accp[i][1]);
            float4 hv = make_float4(__uint_as_float(u0), __uint_as_float(u1),
                                    __uint_as_float(u2), __uint_as_float(u3));
            __half2* dst2 = reinterpret_cast<__half2*>(&g_hh[(size_t)gr * DDIM + o0]);
            dst2[0] = __float22half2_rn(make_float2(hv.x, hv.y));
            dst2[1] = __float22half2_rn(make_float2(hv.z, hv.w));
            float4 ov;
            ov.x = fmaf(hv.x, swv.x, bvv.x);
            ov.y = fmaf(hv.y, swv.y, bvv.y);
            ov.z = fmaf(hv.z, swv.z, bvv.z);
            ov.w = fmaf(hv.w, swv.w, bvv.w);
            *reinterpret_cast<float4*>(&out[(size_t)gr * DDIM + o0]) = ov;
        }
    }
}

// ---------------------------------------------------------------------------
// Kernel 2: single-pass exclusive scan of g_cnt -> g_off / g_fill.
// ---------------------------------------------------------------------------
__global__ void __launch_bounds__(256) scan_kernel(int n)
{
    __shared__ int sv[256];
    __shared__ int sbase;
    const int b = blockIdx.x, t = threadIdx.x;
    const int base = b * SBLK + t * 4;

    int c[4];
    int s = 0;
    #pragma unroll
    for (int k = 0; k < 4; k++) {
        int i = base + k;
        c[k] = (i < n) ? g_cnt[i] : 0;
        s += c[k];
    }
    sv[t] = s;
    if (t == 0) sbase = 0;
    __syncthreads();
    #pragma unroll
    for (int off = 1; off < 256; off <<= 1) {
        int u = (t >= off) ? sv[t - off] : 0;
        __syncthreads();
        sv[t] += u;
        __syncthreads();
    }

    if (t == 0) {
        unsigned long long v = (1ULL << 32) | (unsigned)sv[255];
        atomicExch(&g_aggf[b], v);
    }
    __syncthreads();

    if (t < b) {
        unsigned long long v;
        do {
            v = *((volatile unsigned long long*)&g_aggf[t]);
        } while (!(v >> 32));
        atomicAdd(&sbase, (int)(unsigned)v);
    }
    __syncthreads();

    int run = sbase + sv[t] - s;
    #pragma unroll
    for (int k = 0; k < 4; k++) {
        int i = base + k;
        if (i < n) {
            g_off[i]  = run;
            g_fill[i] = run;
            run += c[k];
        }
    }
}

// ---------------------------------------------------------------------------
// Kernel 3: fill dst-grouped edge arrays; reset scan flags for next replay.
// ---------------------------------------------------------------------------
__global__ void fill_kernel(const int* __restrict__ src,
                            const int* __restrict__ dst,
                            const float* __restrict__ ew, int E)
{
    int i = blockIdx.x * blockDim.x + threadIdx.x;
    if (i < NSB) g_aggf[i] = 0ULL;
    if (i < E) {
        int d = dst[i];
        int slot = atomicAdd(&g_fill[d], 1);
        g_edges[slot] = make_uint2((unsigned)src[i], __float_as_uint(ew[i]));
        g_edst[slot]  = d;
    }
}

// ---------------------------------------------------------------------------
// Kernel 4: segmented scatter. Edges are dst-grouped; each 16-lane group
// walks 16 CONTIGUOUS edges, accumulating in registers while dst repeats,
// firing one red.v4 per dst-change (~2 per run instead of 16).
// ---------------------------------------------------------------------------
#define EPB 256

__global__ void __launch_bounds__(256) scatter_seg_kernel(
    float* __restrict__ out, int E)
{
    __shared__ uint2 sm[EPB];
    __shared__ int   sd[EPB];

    const int tid  = threadIdx.x;
    const int base = blockIdx.x * EPB;

    int ge = base + tid;
    if (ge < E) {
        sm[tid] = g_edges[ge];
        sd[tid] = g_edst[ge];
    }
    __syncthreads();

    const int grp   = tid >> 4;           // 0..15: which 16-edge run
    const int lane4 = (tid & 15) << 2;    // 0,4,...,60
    const int e0    = grp * 16;
    const int m     = min(E - base - e0, 16);
    if (m <= 0) return;

    float4 acc = make_float4(0.0f, 0.0f, 0.0f, 0.0f);

    #pragma unroll
    for (int b = 0; b < 2; b++) {
        const int cnt = min(m - b * 8, 8);
        if (cnt <= 0) break;

        // Phase 1: up to 8 independent gather loads (MLP 8)
        uint2 pk[8];
        #pragma unroll
        for (int q = 0; q < 8; q++) {
            unsigned s = (q < cnt) ? sm[e0 + b * 8 + q].x : 0u;
            pk[q] = *reinterpret_cast<const uint2*>(
                &g_hh[(size_t)s * DDIM + lane4]);
        }

        // Phase 2: accumulate; flush on dst-change or run end
        #pragma unroll
        for (int q = 0; q < 8; q++) {
            if (q >= cnt) break;
            const int k = b * 8 + q;
            const float w = __uint_as_float(sm[e0 + k].y);
            float2 f0 = __half22float2(*reinterpret_cast<const __half2*>(&pk[q].x));
            float2 f1 = __half22float2(*reinterpret_cast<const __half2*>(&pk[q].y));
            acc.x = fmaf(f0.x, w, acc.x);
            acc.y = fmaf(f0.y, w, acc.y);
            acc.z = fmaf(f1.x, w, acc.z);
            acc.w = fmaf(f1.y, w, acc.w);

            const int d = sd[e0 + k];
            const bool flush = (k == m - 1) || (sd[e0 + k + 1] != d);
            if (flush) {
                float* o = out + (size_t)d * DDIM + lane4;
                asm volatile(
                    "red.global.add.v4.f32 [%0], {%1, %2, %3, %4};"
                    :: "l"(o), "f"(acc.x), "f"(acc.y), "f"(acc.z), "f"(acc.w)
                    : "memory");
                acc = make_float4(0.0f, 0.0f, 0.0f, 0.0f);
            }
        }
    }
}

// ---------------------------------------------------------------------------
// Kernel 5: in-place SELU; also re-zeroes g_cnt for the next replay.
// ---------------------------------------------------------------------------
__global__ void __launch_bounds__(256) selu_kernel(float* __restrict__ out,
                                                   int total4, int n)
{
    const float scale = 1.0507009873554805f;
    const float alpha = 1.6732632423543772f;
    int i = blockIdx.x * blockDim.x + threadIdx.x;
    if (i < n) g_cnt[i] = 0;   // restore zero invariant
    if (i >= total4) return;
    float4 v = reinterpret_cast<float4*>(out)[i];
    v.x = v.x > 0.0f ? scale * v.x : scale * alpha * (expf(v.x) - 1.0f);
    v.y = v.y > 0.0f ? scale * v.y : scale * alpha * (expf(v.y) - 1.0f);
    v.z = v.z > 0.0f ? scale * v.z : scale * alpha * (expf(v.z) - 1.0f);
    v.w = v.w > 0.0f ? scale * v.w : scale * alpha * (expf(v.w) - 1.0f);
    reinterpret_cast<float4*>(out)[i] = v;
}

extern "C" void kernel_launch(void* const* d_in, const int* in_sizes, int n_in,
                              void* d_out, int out_size)
{
    const float* features = (const float*)d_in[0];
    const float* W        = (const float*)d_in[1];
    const float* bias     = (const float*)d_in[2];
    const float* skipw    = (const float*)d_in[3];
    const float* ew       = (const float*)d_in[4];
    const int*   esrc     = (const int*)d_in[5];
    const int*   edst     = (const int*)d_in[6];
    float* out = (float*)d_out;

    const int n = in_sizes[0] / DDIM;     // 50000
    const int E = in_sizes[4];            // 800000

    // 1. GEMM + out-init (skip+bias) + fp16 copy + fused histogram
    gemm_skip_kernel<<<GBLKS, 256>>>(features, W, bias, skipw, edst, out, E, n);

    // 2. single-pass scan -> CSR offsets
    scan_kernel<<<NSB, 256>>>(n);

    // 3. group edges by dst
    fill_kernel<<<(E + 511) / 512, 512>>>(esrc, edst, ew, E);

    // 4. segmented scatter (~2 red.v4 per 16-edge run instead of 16)
    scatter_seg_kernel<<<(E + EPB - 1) / EPB, 256>>>(out, E);

    // 5. SELU in place + g_cnt reset
    int total4 = (n * DDIM) / 4;
    selu_kernel<<<(total4 + 255) / 256, 256>>>(out, total4, n);
}